// round 12
// baseline (speedup 1.0000x reference)
#include <cuda_runtime.h>
#include <cuda_bf16.h>
#include <cstdint>

#define BATCH 64
#define SEQ   1024
#define IDIM  256
#define HDIM  512
#define ODIM  128
#define G4    2048

typedef unsigned long long ull;

// ---------------- device scratch ----------------
__device__ float g_xp[(size_t)SEQ * BATCH * G4];          // input projection [t*64+b][4H]
__device__ __nv_bfloat16 g_hh[2][BATCH * HDIM];           // h hi plane, double-buffered
__device__ __nv_bfloat16 g_hl[2][BATCH * HDIM];           // h lo plane
__device__ float g_last[BATCH * 2 * HDIM];
__device__ ull g_flags[128][16];                          // padded barrier flags

__device__ __forceinline__ float sigf(float v) {
    return __fdividef(1.0f, 1.0f + __expf(-v));
}
__device__ __forceinline__ float tanhf_fast(float v) {
    float e = __expf(2.0f * v);
    return __fdividef(e - 1.0f, e + 1.0f);
}
__device__ __forceinline__ uint32_t packbf2(__nv_bfloat16 lo_elem, __nv_bfloat16 hi_elem) {
    return (uint32_t)__bfloat16_as_ushort(lo_elem) |
           ((uint32_t)__bfloat16_as_ushort(hi_elem) << 16);
}
__device__ __forceinline__ void mma16816(
    float& d0, float& d1, float& d2, float& d3,
    uint32_t a0, uint32_t a1, uint32_t a2, uint32_t a3,
    uint32_t b0, uint32_t b1)
{
    asm volatile(
        "mma.sync.aligned.m16n8k16.row.col.f32.bf16.bf16.f32 "
        "{%0,%1,%2,%3},{%4,%5,%6,%7},{%8,%9},{%0,%1,%2,%3};"
        : "+f"(d0), "+f"(d1), "+f"(d2), "+f"(d3)
        : "r"(a0), "r"(a1), "r"(a2), "r"(a3), "r"(b0), "r"(b1));
}
#define LDSM4(r0, r1, r2, r3, addr) \
    asm volatile("ldmatrix.sync.aligned.m8n8.x4.shared.b16 {%0,%1,%2,%3}, [%4];" \
                 : "=r"(r0), "=r"(r1), "=r"(r2), "=r"(r3) : "r"(addr))

// ================================================================
// Kernel 1: xp = relu(x) @ W_ih_f^T + b_f  — TC version (unchanged)
// ================================================================
#define XBM 128
#define XBN 64
#define XBK 64
#define XST 36
#define XGEMM_SMEM ((2*XBM*XST + 2*XBN*XST) * 4)

__global__ void __launch_bounds__(256, 2) gemm_xp_kernel(
    const float* __restrict__ x,
    const float* __restrict__ Wih, const float* __restrict__ bias)
{
    extern __shared__ uint32_t smx[];
    uint32_t* Ah = smx;
    uint32_t* Al = Ah + XBM * XST;
    uint32_t* Bh = Al + XBM * XST;
    uint32_t* Bl = Bh + XBN * XST;

    const int tid  = threadIdx.x;
    const int lane = tid & 31, wid = tid >> 5;
    const int n0 = blockIdx.x * XBN;
    const int t0 = blockIdx.y * 2;

    const int mw = wid >> 1;
    const int nw = wid & 1;
    const int g = lane >> 2, tig = lane & 3;

    float C[2][4][4];
#pragma unroll
    for (int mt = 0; mt < 2; mt++)
#pragma unroll
        for (int nt = 0; nt < 4; nt++)
            C[mt][nt][0] = C[mt][nt][1] = C[mt][nt][2] = C[mt][nt][3] = 0.f;

#pragma unroll 1
    for (int ko = 0; ko < IDIM; ko += XBK) {
#pragma unroll
        for (int i = 0; i < 8; i++) {
            int u = tid + i * 256;
            int row = u >> 4, q = u & 15;
            int b = row & 63, tt = t0 + (row >> 6);
            float4 v = __ldcg((const float4*)(x + ((size_t)b * SEQ + tt) * IDIM + ko + q * 4));
            v.x = fmaxf(v.x, 0.f); v.y = fmaxf(v.y, 0.f);
            v.z = fmaxf(v.z, 0.f); v.w = fmaxf(v.w, 0.f);
            __nv_bfloat16 h0 = __float2bfloat16(v.x), h1 = __float2bfloat16(v.y);
            __nv_bfloat16 h2 = __float2bfloat16(v.z), h3 = __float2bfloat16(v.w);
            __nv_bfloat16 l0 = __float2bfloat16(v.x - __bfloat162float(h0));
            __nv_bfloat16 l1 = __float2bfloat16(v.y - __bfloat162float(h1));
            __nv_bfloat16 l2 = __float2bfloat16(v.z - __bfloat162float(h2));
            __nv_bfloat16 l3 = __float2bfloat16(v.w - __bfloat162float(h3));
            *(uint2*)(Ah + row * XST + q * 2) = make_uint2(packbf2(h0, h1), packbf2(h2, h3));
            *(uint2*)(Al + row * XST + q * 2) = make_uint2(packbf2(l0, l1), packbf2(l2, l3));
        }
#pragma unroll
        for (int i = 0; i < 4; i++) {
            int u = tid + i * 256;
            int row = u >> 4, q = u & 15;
            float4 v = __ldcg((const float4*)(Wih + (size_t)(n0 + row) * IDIM + ko + q * 4));
            __nv_bfloat16 h0 = __float2bfloat16(v.x), h1 = __float2bfloat16(v.y);
            __nv_bfloat16 h2 = __float2bfloat16(v.z), h3 = __float2bfloat16(v.w);
            __nv_bfloat16 l0 = __float2bfloat16(v.x - __bfloat162float(h0));
            __nv_bfloat16 l1 = __float2bfloat16(v.y - __bfloat162float(h1));
            __nv_bfloat16 l2 = __float2bfloat16(v.z - __bfloat162float(h2));
            __nv_bfloat16 l3 = __float2bfloat16(v.w - __bfloat162float(h3));
            *(uint2*)(Bh + row * XST + q * 2) = make_uint2(packbf2(h0, h1), packbf2(h2, h3));
            *(uint2*)(Bl + row * XST + q * 2) = make_uint2(packbf2(l0, l1), packbf2(l2, l3));
        }
        __syncthreads();

#pragma unroll
        for (int ks = 0; ks < 4; ks++) {
            int w = ks * 8;
            uint32_t bh[4][2], bl[4][2];
#pragma unroll
            for (int nt = 0; nt < 4; nt++) {
                int c = (nw * 32 + nt * 8 + g) * XST + w + tig;
                bh[nt][0] = Bh[c]; bh[nt][1] = Bh[c + 4];
                bl[nt][0] = Bl[c]; bl[nt][1] = Bl[c + 4];
            }
#pragma unroll
            for (int mt = 0; mt < 2; mt++) {
                int r0 = (mw * 32 + mt * 16 + g) * XST + w + tig;
                int r1 = r0 + 8 * XST;
                uint32_t ah0 = Ah[r0], ah1 = Ah[r1], ah2 = Ah[r0 + 4], ah3 = Ah[r1 + 4];
                uint32_t al0 = Al[r0], al1 = Al[r1], al2 = Al[r0 + 4], al3 = Al[r1 + 4];
#pragma unroll
                for (int nt = 0; nt < 4; nt++) {
                    mma16816(C[mt][nt][0], C[mt][nt][1], C[mt][nt][2], C[mt][nt][3],
                             ah0, ah1, ah2, ah3, bh[nt][0], bh[nt][1]);
                    mma16816(C[mt][nt][0], C[mt][nt][1], C[mt][nt][2], C[mt][nt][3],
                             al0, al1, al2, al3, bh[nt][0], bh[nt][1]);
                    mma16816(C[mt][nt][0], C[mt][nt][1], C[mt][nt][2], C[mt][nt][3],
                             ah0, ah1, ah2, ah3, bl[nt][0], bl[nt][1]);
                }
            }
        }
        __syncthreads();
    }

#pragma unroll
    for (int mt = 0; mt < 2; mt++) {
#pragma unroll
        for (int nt = 0; nt < 4; nt++) {
            int col = n0 + nw * 32 + nt * 8 + tig * 2;
            float2 bv = *(const float2*)(bias + col);
            int ml = mw * 32 + mt * 16 + g;
            int rowg = (t0 + (ml >> 6)) * BATCH + (ml & 63);
            float2 o0 = { C[mt][nt][0] + bv.x, C[mt][nt][1] + bv.y };
            *(float2*)(g_xp + (size_t)rowg * G4 + col) = o0;
            ml += 8;
            rowg = (t0 + (ml >> 6)) * BATCH + (ml & 63);
            float2 o1 = { C[mt][nt][2] + bv.x, C[mt][nt][3] + bv.y };
            *(float2*)(g_xp + (size_t)rowg * G4 + col) = o1;
        }
    }
}

// ================================================================
// Kernel 2: backward-direction last hidden state (unchanged)
// ================================================================
__global__ void __launch_bounds__(256) bwd_last_kernel(
    const float* __restrict__ x,
    const float* __restrict__ Wb, const float* __restrict__ bb)
{
    __shared__ float xs[IDIM];
    const int b = blockIdx.x, tid = threadIdx.x;
    xs[tid] = fmaxf(x[((size_t)b * SEQ + (SEQ - 1)) * IDIM + tid], 0.f);
    __syncthreads();

    const int j = blockIdx.y * 256 + tid;
    const int cols[3] = { j, 2 * HDIM + j, 3 * HDIM + j };
    float acc[3] = { bb[cols[0]], bb[cols[1]], bb[cols[2]] };
#pragma unroll
    for (int gi = 0; gi < 3; gi++) {
        const float4* wp = (const float4*)(Wb + (size_t)cols[gi] * IDIM);
        float s = 0.f;
#pragma unroll 8
        for (int k4 = 0; k4 < IDIM / 4; k4++) {
            float4 w = __ldg(wp + k4);
            float4 xv = *(const float4*)&xs[k4 * 4];
            s += w.x * xv.x + w.y * xv.y + w.z * xv.z + w.w * xv.w;
        }
        acc[gi] += s;
    }
    float cst = sigf(acc[0]) * tanhf_fast(acc[1]);
    float h   = sigf(acc[2]) * tanhf_fast(cst);
    g_last[b * (2 * HDIM) + HDIM + j] = h;
}

// ================================================================
// Kernel 3: persistent LSTM scan — ldmatrix + warp-owned gate cols.
// 128 blocks = 4 batch-groups x 32 j-groups; 256 threads (8 warps).
// Warp w owns gate cols {gate*512 + jg*16 + 2w + jl} (4 gates x 2
// H-cols) over FULL k=512: computes complete gate sums -> update is
// warp-local (no block-wide gs exchange, one less syncthreads).
// Fragment loads via ldmatrix.x4 (96 LDSM vs 256 LDS per thread).
// 6 fp32 accumulators (3 precision variants x kstep parity).
// ================================================================
#define SCAN_BLOCKS 128
#define SCAN_THREADS 256
#define WST 260                 // words per 512-elem bf16 row (256 + 4 pad)
#define GW 9                    // gwarp pitch (conflict-free reads)
#define SCAN_SMEM ((2*64*WST + 2*16*WST + 8*16*GW) * 4)

__global__ void __launch_bounds__(SCAN_THREADS, 1) lstm_scan_kernel(const float* __restrict__ Whh)
{
    extern __shared__ uint32_t smw[];
    uint32_t* ws_hi = smw;                    // [64][WST]  W hi (rows permuted per warp)
    uint32_t* ws_lo = smw + 64 * WST;         // [64][WST]  W lo
    uint32_t* hs_hi = smw + 2 * 64 * WST;     // [16][WST]  h hi
    uint32_t* hs_lo = hs_hi + 16 * WST;       // [16][WST]  h lo
    float*    gw    = (float*)(hs_lo + 16 * WST);  // [8][16][GW] warp-local gates

    const int tid  = threadIdx.x;
    const int bid  = blockIdx.x;
    const int bg   = bid >> 5;
    const int jg   = bid & 31;
    const int fbase = bg * 32;
    const int lane = tid & 31;
    const int wid  = tid >> 5;

    // ---- one-time W_hh load: ws row (wv*8 + gate*2 + jl) = that col's k ----
#pragma unroll 1
    for (int u = tid; u < 64 * 256; u += SCAN_THREADS) {
        int lr = u >> 8;                     // ws row 0..63
        int w  = u & 255;                    // word (2 k-elems)
        int wv = lr >> 3, c = lr & 7;
        int gate = c >> 1, jl = c & 1;
        int grow = gate * HDIM + jg * 16 + 2 * wv + jl;
        float2 v = *(const float2*)(Whh + (size_t)grow * HDIM + w * 2);
        __nv_bfloat16 h0 = __float2bfloat16(v.x);
        __nv_bfloat16 h1 = __float2bfloat16(v.y);
        __nv_bfloat16 l0 = __float2bfloat16(v.x - __bfloat162float(h0));
        __nv_bfloat16 l1 = __float2bfloat16(v.y - __bfloat162float(h1));
        ws_hi[lr * WST + w] = packbf2(h0, h1);
        ws_lo[lr * WST + w] = packbf2(l0, l1);
    }

    // ---- ldmatrix per-lane base addresses (shared-space bytes) ----
    const int arow = ((lane >> 3) & 1) * 8 + (lane & 7);
    const int aoff = (lane >> 4) * 4;            // words
    const uint32_t a_hi = (uint32_t)__cvta_generic_to_shared(hs_hi) + (arow * WST + aoff) * 4;
    const uint32_t a_lo = (uint32_t)__cvta_generic_to_shared(hs_lo) + (arow * WST + aoff) * 4;
    const int brow = wid * 8 + (lane & 7);
    const int boff = (lane >> 3) * 4;            // words
    const uint32_t b_hi = (uint32_t)__cvta_generic_to_shared(ws_hi) + (brow * WST + boff) * 4;
    const uint32_t b_lo = (uint32_t)__cvta_generic_to_shared(ws_lo) + (brow * WST + boff) * 4;

    const int g = lane >> 2, tig = lane & 3;
    float* gwp = gw + wid * 16 * GW;

    // ---- update role: lane L -> (batch = bg*16 + L>>1, jcol = jg*16 + 2*wid + (L&1)) ----
    const int ub = lane >> 1, ujl = lane & 1;
    const int batch = bg * 16 + ub;
    const int jcol  = jg * 16 + 2 * wid + ujl;
    float cstate = 0.f;
    __nv_bfloat16* hh0 = &g_hh[0][batch * HDIM + jcol];
    __nv_bfloat16* hh1 = &g_hh[1][batch * HDIM + jcol];
    __nv_bfloat16* hl0 = &g_hl[0][batch * HDIM + jcol];
    __nv_bfloat16* hl1 = &g_hl[1][batch * HDIM + jcol];
    const size_t tstride = (size_t)BATCH * G4;
    const float* xpi = g_xp + (size_t)batch * G4 + 0 * HDIM + jcol;
    const float* xpf = g_xp + (size_t)batch * G4 + 1 * HDIM + jcol;
    const float* xpg = g_xp + (size_t)batch * G4 + 2 * HDIM + jcol;
    const float* xpo = g_xp + (size_t)batch * G4 + 3 * HDIM + jcol;
    float xvi = __ldcs(xpi), xvf = __ldcs(xpf);
    float xvg = __ldcs(xpg), xvo = __ldcs(xpo);

    // ---- t = 0: h = 0 -> gates = xp ----
    {
        float i_ = sigf(xvi), f_ = sigf(xvf);
        float gv = tanhf_fast(xvg), o_ = sigf(xvo);
        cstate = fmaf(f_, cstate, i_ * gv);
        float h = o_ * tanhf_fast(cstate);
        __nv_bfloat16 hhi = __float2bfloat16(h);
        __nv_bfloat16 hlo = __float2bfloat16(h - __bfloat162float(hhi));
        *hh1 = hhi; *hl1 = hlo;
        xvi = __ldcs(xpi + tstride); xvf = __ldcs(xpf + tstride);
        xvg = __ldcs(xpg + tstride); xvo = __ldcs(xpo + tstride);
    }

#define FLAGBAR(VAL) do{                                                       \
    __syncthreads();                                                           \
    if (tid == 0)                                                              \
        asm volatile("st.release.gpu.global.u64 [%0], %1;"                     \
                     :: "l"(&g_flags[bid][0]), "l"((ull)(VAL)) : "memory");    \
    {                                                                          \
        ull v;                                                                 \
        do {                                                                   \
            asm volatile("ld.acquire.gpu.global.u64 %0, [%1];"                 \
                         : "=l"(v) : "l"(&g_flags[fbase + lane][0]) : "memory"); \
        } while (v < (ull)(VAL));                                              \
        __syncwarp();                                                          \
    }                                                                          \
}while(0)

    FLAGBAR(1);

#pragma unroll 1
    for (int t = 1; t < SEQ; t++) {
        // ---- stage h hi/lo slab (16 batches x 512): 4 x uint4/thread/plane ----
        const uint4* srch = (const uint4*)(g_hh[t & 1] + (size_t)bg * 16 * HDIM);
        const uint4* srcl = (const uint4*)(g_hl[t & 1] + (size_t)bg * 16 * HDIM);
#pragma unroll
        for (int i = 0; i < 4; i++) {
            int u = tid + i * SCAN_THREADS;
            int b  = u >> 6;
            int w0 = (u & 63) * 4;
            uint4 v = __ldcg(srch + u);
            *(uint4*)(hs_hi + b * WST + w0) = v;
            v = __ldcg(srcl + u);
            *(uint4*)(hs_lo + b * WST + w0) = v;
        }
        __syncthreads();

        // ---- MMAs: 16 iters x (2 ksteps x 3 variants); ldmatrix fragments ----
        float D[6][4];
#pragma unroll
        for (int i = 0; i < 6; i++)
            D[i][0] = D[i][1] = D[i][2] = D[i][3] = 0.f;

#pragma unroll 4
        for (int it = 0; it < 16; it++) {
            const uint32_t kb = it * 64;         // byte offset (16 words per iter)
            uint32_t bh0, bh1, bh2, bh3, bl0, bl1, bl2, bl3;
            LDSM4(bh0, bh1, bh2, bh3, b_hi + kb);
            LDSM4(bl0, bl1, bl2, bl3, b_lo + kb);
            uint32_t ah0, ah1, ah2, ah3, ah4, ah5, ah6, ah7;
            uint32_t al0, al1, al2, al3, al4, al5, al6, al7;
            LDSM4(ah0, ah1, ah2, ah3, a_hi + kb);
            LDSM4(al0, al1, al2, al3, a_lo + kb);
            LDSM4(ah4, ah5, ah6, ah7, a_hi + kb + 32);
            LDSM4(al4, al5, al6, al7, a_lo + kb + 32);
            // kstep 0 (parity 0)
            mma16816(D[0][0], D[0][1], D[0][2], D[0][3], ah0, ah1, ah2, ah3, bh0, bh1);
            mma16816(D[1][0], D[1][1], D[1][2], D[1][3], al0, al1, al2, al3, bh0, bh1);
            mma16816(D[2][0], D[2][1], D[2][2], D[2][3], ah0, ah1, ah2, ah3, bl0, bl1);
            // kstep 1 (parity 1)
            mma16816(D[3][0], D[3][1], D[3][2], D[3][3], ah4, ah5, ah6, ah7, bh2, bh3);
            mma16816(D[4][0], D[4][1], D[4][2], D[4][3], al4, al5, al6, al7, bh2, bh3);
            mma16816(D[5][0], D[5][1], D[5][2], D[5][3], ah4, ah5, ah6, ah7, bl2, bl3);
        }

        // ---- warp-local gate exchange + update ----
        {
            float s0 = D[0][0] + D[1][0] + D[2][0] + D[3][0] + D[4][0] + D[5][0];
            float s1 = D[0][1] + D[1][1] + D[2][1] + D[3][1] + D[4][1] + D[5][1];
            float s2 = D[0][2] + D[1][2] + D[2][2] + D[3][2] + D[4][2] + D[5][2];
            float s3 = D[0][3] + D[1][3] + D[2][3] + D[3][3] + D[4][3] + D[5][3];
            gwp[g * GW + 2 * tig + 0] = s0;
            gwp[g * GW + 2 * tig + 1] = s1;
            gwp[(g + 8) * GW + 2 * tig + 0] = s2;
            gwp[(g + 8) * GW + 2 * tig + 1] = s3;
        }
        __syncwarp();
        {
            const float* gr = gwp + ub * GW + ujl;
            float gi = gr[0] + xvi;
            float gf = gr[2] + xvf;
            float gg = gr[4] + xvg;
            float go = gr[6] + xvo;
            float i_ = sigf(gi), f_ = sigf(gf);
            float gv = tanhf_fast(gg), o_ = sigf(go);
            cstate = fmaf(f_, cstate, i_ * gv);
            float h = o_ * tanhf_fast(cstate);
            __nv_bfloat16 hhi = __float2bfloat16(h);
            __nv_bfloat16 hlo = __float2bfloat16(h - __bfloat162float(hhi));
            if (t & 1) { *hh0 = hhi; *hl0 = hlo; }
            else       { *hh1 = hhi; *hl1 = hlo; }
            if (t == SEQ - 1)
                g_last[batch * (2 * HDIM) + jcol] = h;
            else {
                const size_t off = tstride * (size_t)(t + 1);
                xvi = __ldcs(xpi + off); xvf = __ldcs(xpf + off);
                xvg = __ldcs(xpg + off); xvo = __ldcs(xpo + off);
            }
        }

        if (t < SEQ - 1)
            FLAGBAR(t + 1);
    }
}

// ================================================================
// Kernel 3b: reset barrier flags (stream-ordered after the scan).
// ================================================================
__global__ void reset_flags_kernel()
{
    if (threadIdx.x < 128) g_flags[threadIdx.x][0] = 0ull;
}

// ================================================================
// Kernel 4: final FC (unchanged).
// ================================================================
__global__ void __launch_bounds__(512) fc_kernel(
    const float* __restrict__ Wfc, const float* __restrict__ bfc,
    float* __restrict__ out)
{
    __shared__ float ls[2 * HDIM];
    const int b = blockIdx.x, tid = threadIdx.x;
    if (tid < 256)
        ((float4*)ls)[tid] = ((const float4*)(g_last + (size_t)b * 2 * HDIM))[tid];
    __syncthreads();

    const int o = tid >> 2, q = tid & 3;
    const float4* wp = (const float4*)(Wfc + (size_t)o * (2 * HDIM)) + q * 64;
    const float4* lv = (const float4*)ls + q * 64;
    float acc = 0.f;
#pragma unroll 16
    for (int k = 0; k < 64; k++) {
        float4 w = __ldg(wp + k);
        float4 l = lv[k];
        acc += w.x * l.x + w.y * l.y + w.z * l.z + w.w * l.w;
    }
    acc += __shfl_xor_sync(0xffffffff, acc, 1);
    acc += __shfl_xor_sync(0xffffffff, acc, 2);
    if (q == 0) out[b * ODIM + o] = acc + bfc[o];
}

// ================================================================
extern "C" void kernel_launch(void* const* d_in, const int* in_sizes, int n_in,
                              void* d_out, int out_size)
{
    const float* x      = (const float*)d_in[0];
    const float* W_ih_f = (const float*)d_in[1];
    const float* W_hh_f = (const float*)d_in[2];
    const float* b_f    = (const float*)d_in[3];
    const float* W_ih_b = (const float*)d_in[4];
    const float* b_b    = (const float*)d_in[6];
    const float* W_fc   = (const float*)d_in[7];
    const float* b_fc   = (const float*)d_in[8];
    float* out = (float*)d_out;

    cudaFuncSetAttribute(gemm_xp_kernel,
                         cudaFuncAttributeMaxDynamicSharedMemorySize, XGEMM_SMEM);
    cudaFuncSetAttribute(lstm_scan_kernel,
                         cudaFuncAttributeMaxDynamicSharedMemorySize, SCAN_SMEM);

    gemm_xp_kernel<<<dim3(G4 / XBN, SEQ / 2), 256, XGEMM_SMEM>>>(x, W_ih_f, b_f);
    bwd_last_kernel<<<dim3(BATCH, 2), 256>>>(x, W_ih_b, b_b);
    lstm_scan_kernel<<<SCAN_BLOCKS, SCAN_THREADS, SCAN_SMEM>>>(W_hh_f);
    reset_flags_kernel<<<1, 128>>>();
    fc_kernel<<<BATCH, 512>>>(W_fc, b_fc, out);
}

// round 15
// speedup vs baseline: 1.2480x; 1.2480x over previous
#include <cuda_runtime.h>
#include <cuda_bf16.h>
#include <cstdint>

#define BATCH 64
#define SEQ   1024
#define IDIM  256
#define HDIM  512
#define ODIM  128
#define G4    2048

typedef unsigned long long ull;

// ---------------- device scratch ----------------
__device__ float g_xp[(size_t)SEQ * BATCH * G4];          // input projection [t*64+b][4H]
__device__ __nv_bfloat16 g_hh[2][BATCH * HDIM];           // h (bf16), double-buffered
__device__ float g_last[BATCH * 2 * HDIM];
__device__ ull g_flags[128][16];                          // padded barrier flags

__device__ __forceinline__ float sigf(float v) {
    return __fdividef(1.0f, 1.0f + __expf(-v));
}
__device__ __forceinline__ float tanhf_fast(float v) {
    float e = __expf(2.0f * v);
    return __fdividef(e - 1.0f, e + 1.0f);
}
__device__ __forceinline__ uint32_t packbf2(__nv_bfloat16 lo_elem, __nv_bfloat16 hi_elem) {
    return (uint32_t)__bfloat16_as_ushort(lo_elem) |
           ((uint32_t)__bfloat16_as_ushort(hi_elem) << 16);
}
__device__ __forceinline__ void mma16816(
    float& d0, float& d1, float& d2, float& d3,
    uint32_t a0, uint32_t a1, uint32_t a2, uint32_t a3,
    uint32_t b0, uint32_t b1)
{
    asm volatile(
        "mma.sync.aligned.m16n8k16.row.col.f32.bf16.bf16.f32 "
        "{%0,%1,%2,%3},{%4,%5,%6,%7},{%8,%9},{%0,%1,%2,%3};"
        : "+f"(d0), "+f"(d1), "+f"(d2), "+f"(d3)
        : "r"(a0), "r"(a1), "r"(a2), "r"(a3), "r"(b0), "r"(b1));
}

// ================================================================
// Kernel 1: xp = relu(x) @ W_ih_f^T + b_f  — TC version (unchanged)
// ================================================================
#define XBM 128
#define XBN 64
#define XBK 64
#define XST 36
#define XGEMM_SMEM ((2*XBM*XST + 2*XBN*XST) * 4)

__global__ void __launch_bounds__(256, 2) gemm_xp_kernel(
    const float* __restrict__ x,
    const float* __restrict__ Wih, const float* __restrict__ bias)
{
    extern __shared__ uint32_t smx[];
    uint32_t* Ah = smx;
    uint32_t* Al = Ah + XBM * XST;
    uint32_t* Bh = Al + XBM * XST;
    uint32_t* Bl = Bh + XBN * XST;

    const int tid  = threadIdx.x;
    const int lane = tid & 31, wid = tid >> 5;
    const int n0 = blockIdx.x * XBN;
    const int t0 = blockIdx.y * 2;

    const int mw = wid >> 1;
    const int nw = wid & 1;
    const int g = lane >> 2, tig = lane & 3;

    float C[2][4][4];
#pragma unroll
    for (int mt = 0; mt < 2; mt++)
#pragma unroll
        for (int nt = 0; nt < 4; nt++)
            C[mt][nt][0] = C[mt][nt][1] = C[mt][nt][2] = C[mt][nt][3] = 0.f;

#pragma unroll 1
    for (int ko = 0; ko < IDIM; ko += XBK) {
#pragma unroll
        for (int i = 0; i < 8; i++) {
            int u = tid + i * 256;
            int row = u >> 4, q = u & 15;
            int b = row & 63, tt = t0 + (row >> 6);
            float4 v = __ldcg((const float4*)(x + ((size_t)b * SEQ + tt) * IDIM + ko + q * 4));
            v.x = fmaxf(v.x, 0.f); v.y = fmaxf(v.y, 0.f);
            v.z = fmaxf(v.z, 0.f); v.w = fmaxf(v.w, 0.f);
            __nv_bfloat16 h0 = __float2bfloat16(v.x), h1 = __float2bfloat16(v.y);
            __nv_bfloat16 h2 = __float2bfloat16(v.z), h3 = __float2bfloat16(v.w);
            __nv_bfloat16 l0 = __float2bfloat16(v.x - __bfloat162float(h0));
            __nv_bfloat16 l1 = __float2bfloat16(v.y - __bfloat162float(h1));
            __nv_bfloat16 l2 = __float2bfloat16(v.z - __bfloat162float(h2));
            __nv_bfloat16 l3 = __float2bfloat16(v.w - __bfloat162float(h3));
            *(uint2*)(Ah + row * XST + q * 2) = make_uint2(packbf2(h0, h1), packbf2(h2, h3));
            *(uint2*)(Al + row * XST + q * 2) = make_uint2(packbf2(l0, l1), packbf2(l2, l3));
        }
#pragma unroll
        for (int i = 0; i < 4; i++) {
            int u = tid + i * 256;
            int row = u >> 4, q = u & 15;
            float4 v = __ldcg((const float4*)(Wih + (size_t)(n0 + row) * IDIM + ko + q * 4));
            __nv_bfloat16 h0 = __float2bfloat16(v.x), h1 = __float2bfloat16(v.y);
            __nv_bfloat16 h2 = __float2bfloat16(v.z), h3 = __float2bfloat16(v.w);
            __nv_bfloat16 l0 = __float2bfloat16(v.x - __bfloat162float(h0));
            __nv_bfloat16 l1 = __float2bfloat16(v.y - __bfloat162float(h1));
            __nv_bfloat16 l2 = __float2bfloat16(v.z - __bfloat162float(h2));
            __nv_bfloat16 l3 = __float2bfloat16(v.w - __bfloat162float(h3));
            *(uint2*)(Bh + row * XST + q * 2) = make_uint2(packbf2(h0, h1), packbf2(h2, h3));
            *(uint2*)(Bl + row * XST + q * 2) = make_uint2(packbf2(l0, l1), packbf2(l2, l3));
        }
        __syncthreads();

#pragma unroll
        for (int ks = 0; ks < 4; ks++) {
            int w = ks * 8;
            uint32_t bh[4][2], bl[4][2];
#pragma unroll
            for (int nt = 0; nt < 4; nt++) {
                int c = (nw * 32 + nt * 8 + g) * XST + w + tig;
                bh[nt][0] = Bh[c]; bh[nt][1] = Bh[c + 4];
                bl[nt][0] = Bl[c]; bl[nt][1] = Bl[c + 4];
            }
#pragma unroll
            for (int mt = 0; mt < 2; mt++) {
                int r0 = (mw * 32 + mt * 16 + g) * XST + w + tig;
                int r1 = r0 + 8 * XST;
                uint32_t ah0 = Ah[r0], ah1 = Ah[r1], ah2 = Ah[r0 + 4], ah3 = Ah[r1 + 4];
                uint32_t al0 = Al[r0], al1 = Al[r1], al2 = Al[r0 + 4], al3 = Al[r1 + 4];
#pragma unroll
                for (int nt = 0; nt < 4; nt++) {
                    mma16816(C[mt][nt][0], C[mt][nt][1], C[mt][nt][2], C[mt][nt][3],
                             ah0, ah1, ah2, ah3, bh[nt][0], bh[nt][1]);
                    mma16816(C[mt][nt][0], C[mt][nt][1], C[mt][nt][2], C[mt][nt][3],
                             al0, al1, al2, al3, bh[nt][0], bh[nt][1]);
                    mma16816(C[mt][nt][0], C[mt][nt][1], C[mt][nt][2], C[mt][nt][3],
                             ah0, ah1, ah2, ah3, bl[nt][0], bl[nt][1]);
                }
            }
        }
        __syncthreads();
    }

#pragma unroll
    for (int mt = 0; mt < 2; mt++) {
#pragma unroll
        for (int nt = 0; nt < 4; nt++) {
            int col = n0 + nw * 32 + nt * 8 + tig * 2;
            float2 bv = *(const float2*)(bias + col);
            int ml = mw * 32 + mt * 16 + g;
            int rowg = (t0 + (ml >> 6)) * BATCH + (ml & 63);
            float2 o0 = { C[mt][nt][0] + bv.x, C[mt][nt][1] + bv.y };
            *(float2*)(g_xp + (size_t)rowg * G4 + col) = o0;
            ml += 8;
            rowg = (t0 + (ml >> 6)) * BATCH + (ml & 63);
            float2 o1 = { C[mt][nt][2] + bv.x, C[mt][nt][3] + bv.y };
            *(float2*)(g_xp + (size_t)rowg * G4 + col) = o1;
        }
    }
}

// ================================================================
// Kernel 2: backward-direction last hidden state (unchanged)
// ================================================================
__global__ void __launch_bounds__(256) bwd_last_kernel(
    const float* __restrict__ x,
    const float* __restrict__ Wb, const float* __restrict__ bb)
{
    __shared__ float xs[IDIM];
    const int b = blockIdx.x, tid = threadIdx.x;
    xs[tid] = fmaxf(x[((size_t)b * SEQ + (SEQ - 1)) * IDIM + tid], 0.f);
    __syncthreads();

    const int j = blockIdx.y * 256 + tid;
    const int cols[3] = { j, 2 * HDIM + j, 3 * HDIM + j };
    float acc[3] = { bb[cols[0]], bb[cols[1]], bb[cols[2]] };
#pragma unroll
    for (int gi = 0; gi < 3; gi++) {
        const float4* wp = (const float4*)(Wb + (size_t)cols[gi] * IDIM);
        float s = 0.f;
#pragma unroll 8
        for (int k4 = 0; k4 < IDIM / 4; k4++) {
            float4 w = __ldg(wp + k4);
            float4 xv = *(const float4*)&xs[k4 * 4];
            s += w.x * xv.x + w.y * xv.y + w.z * xv.z + w.w * xv.w;
        }
        acc[gi] += s;
    }
    float cst = sigf(acc[0]) * tanhf_fast(acc[1]);
    float h   = sigf(acc[2]) * tanhf_fast(cst);
    g_last[b * (2 * HDIM) + HDIM + j] = h;
}

// ================================================================
// Kernel 3: persistent LSTM scan — R11 structure, h as SINGLE bf16
// plane (W keeps hi/lo -> 2 MMA variants: h*W_hi + h*W_lo).
// 128 blocks = 4 batch-groups x 32 j-groups; 256 threads (8 warps).
// Warp (kh, nw): k-half x 16-col n-group; per-k-half gate partials
// in gs2, summed in update phase. c-state in fp32 regs; h is
// requantized from fp32 each step (no error compounding through h).
// FIX vs R14: h staging covers all 1024 uint4 (4 iters, not 2).
// ================================================================
#define SCAN_BLOCKS 128
#define SCAN_THREADS 256
#define WST 260                 // words per 512-elem bf16 row (256 + 4 pad)
#define GSP 68
#define SCAN_SMEM ((2*64*WST + 16*WST + 2*16*GSP) * 4)

__global__ void __launch_bounds__(SCAN_THREADS, 1) lstm_scan_kernel(const float* __restrict__ Whh)
{
    extern __shared__ uint32_t smw[];
    uint32_t* ws_hi = smw;                    // [64][WST]
    uint32_t* ws_lo = smw + 64 * WST;
    uint32_t* hs    = smw + 2 * 64 * WST;     // [16][WST] h (bf16)
    float*    gs2   = (float*)(hs + 16 * WST);  // [2][16][GSP]

    const int tid  = threadIdx.x;
    const int bid  = blockIdx.x;
    const int bg   = bid >> 5;
    const int jg   = bid & 31;
    const int fbase = bg * 32;
    const int lane = tid & 31;
    const int wid  = tid >> 5;

    // ---- one-time W_hh slice load + hi/lo split ----
#pragma unroll 1
    for (int u = tid; u < 64 * 256; u += SCAN_THREADS) {
        int lc = u >> 8;
        int w  = u & 255;
        int grow = (lc >> 4) * HDIM + jg * 16 + (lc & 15);
        float2 v = *(const float2*)(Whh + (size_t)grow * HDIM + w * 2);
        __nv_bfloat16 h0 = __float2bfloat16(v.x);
        __nv_bfloat16 h1 = __float2bfloat16(v.y);
        __nv_bfloat16 l0 = __float2bfloat16(v.x - __bfloat162float(h0));
        __nv_bfloat16 l1 = __float2bfloat16(v.y - __bfloat162float(h1));
        ws_hi[lc * WST + w] = packbf2(h0, h1);
        ws_lo[lc * WST + w] = packbf2(l0, l1);
    }

    const int g   = lane >> 2, tig = lane & 3;
    const int kh  = wid >> 2;
    const int nw  = wid & 3;
    const int nc0 = nw * 16;
    const int hb0 = g * WST + tig;
    const int hb1 = (g + 8) * WST + tig;
    const int wb0 = (nc0 + g) * WST + tig;
    const int wb1 = (nc0 + 8 + g) * WST + tig;
    const int kw0 = kh * 128;
    float* gso = gs2 + kh * 16 * GSP;

    const int ub = tid >> 4, uj = tid & 15;
    const int batch = bg * 16 + ub;
    const int jcol  = jg * 16 + uj;
    float cstate = 0.f;
    __nv_bfloat16* hh0 = &g_hh[0][batch * HDIM + jcol];
    __nv_bfloat16* hh1 = &g_hh[1][batch * HDIM + jcol];
    const size_t tstride = (size_t)BATCH * G4;
    const float* xpi = g_xp + (size_t)batch * G4 + 0 * HDIM + jcol;
    const float* xpf = g_xp + (size_t)batch * G4 + 1 * HDIM + jcol;
    const float* xpg = g_xp + (size_t)batch * G4 + 2 * HDIM + jcol;
    const float* xpo = g_xp + (size_t)batch * G4 + 3 * HDIM + jcol;
    float xvi = __ldcs(xpi), xvf = __ldcs(xpf);
    float xvg = __ldcs(xpg), xvo = __ldcs(xpo);

    // ---- t = 0: h = 0 -> gates = xp ----
    {
        float i_ = sigf(xvi), f_ = sigf(xvf);
        float gv = tanhf_fast(xvg), o_ = sigf(xvo);
        cstate = fmaf(f_, cstate, i_ * gv);
        float h = o_ * tanhf_fast(cstate);
        *hh1 = __float2bfloat16(h);
        xvi = __ldcs(xpi + tstride); xvf = __ldcs(xpf + tstride);
        xvg = __ldcs(xpg + tstride); xvo = __ldcs(xpo + tstride);
    }

#define FLAGBAR(VAL) do{                                                       \
    __syncthreads();                                                           \
    if (tid == 0)                                                              \
        asm volatile("st.release.gpu.global.u64 [%0], %1;"                     \
                     :: "l"(&g_flags[bid][0]), "l"((ull)(VAL)) : "memory");    \
    {                                                                          \
        ull v;                                                                 \
        do {                                                                   \
            asm volatile("ld.acquire.gpu.global.u64 %0, [%1];"                 \
                         : "=l"(v) : "l"(&g_flags[fbase + lane][0]) : "memory"); \
        } while (v < (ull)(VAL));                                              \
        __syncwarp();                                                          \
    }                                                                          \
}while(0)

    FLAGBAR(1);

#pragma unroll 1
    for (int t = 1; t < SEQ; t++) {
        // ---- stage h slab: 16 batches x 512 bf16 = 1024 uint4, 4 per thread ----
        const uint4* srch = (const uint4*)(g_hh[t & 1] + (size_t)bg * 16 * HDIM);
#pragma unroll
        for (int i = 0; i < 4; i++) {
            int u = tid + i * SCAN_THREADS;   // uint4 index 0..1023; 64 per batch row
            int b  = u >> 6;
            int w0 = (u & 63) * 4;
            uint4 v = __ldcg(srch + u);
            *(uint4*)(hs + b * WST + w0) = v;
        }
        __syncthreads();

        // ---- dots: 16 k-tiles x 2 n-tiles x 2 variants (h*Whi + h*Wlo) ----
        float D[4][4];
#pragma unroll
        for (int i = 0; i < 4; i++)
            D[i][0] = D[i][1] = D[i][2] = D[i][3] = 0.f;

#pragma unroll 4
        for (int j = 0; j < 16; j++) {
            int w = kw0 + j * 8;
            uint32_t ah0 = hs[hb0 + w],     ah1 = hs[hb1 + w];
            uint32_t ah2 = hs[hb0 + w + 4], ah3 = hs[hb1 + w + 4];
            uint32_t bh00 = ws_hi[wb0 + w], bh01 = ws_hi[wb0 + w + 4];
            uint32_t bl00 = ws_lo[wb0 + w], bl01 = ws_lo[wb0 + w + 4];
            uint32_t bh10 = ws_hi[wb1 + w], bh11 = ws_hi[wb1 + w + 4];
            uint32_t bl10 = ws_lo[wb1 + w], bl11 = ws_lo[wb1 + w + 4];
            mma16816(D[0][0], D[0][1], D[0][2], D[0][3], ah0, ah1, ah2, ah3, bh00, bh01);
            mma16816(D[1][0], D[1][1], D[1][2], D[1][3], ah0, ah1, ah2, ah3, bl00, bl01);
            mma16816(D[2][0], D[2][1], D[2][2], D[2][3], ah0, ah1, ah2, ah3, bh10, bh11);
            mma16816(D[3][0], D[3][1], D[3][2], D[3][3], ah0, ah1, ah2, ah3, bl10, bl11);
        }

        // ---- epilogue: combine variants, store to this k-half's gs plane ----
        {
            float s0, s1, s2, s3;
            s0 = D[0][0] + D[1][0];
            s1 = D[0][1] + D[1][1];
            s2 = D[0][2] + D[1][2];
            s3 = D[0][3] + D[1][3];
            gso[g * GSP + nc0 + tig * 2 + 0] = s0;
            gso[g * GSP + nc0 + tig * 2 + 1] = s1;
            gso[(g + 8) * GSP + nc0 + tig * 2 + 0] = s2;
            gso[(g + 8) * GSP + nc0 + tig * 2 + 1] = s3;
            s0 = D[2][0] + D[3][0];
            s1 = D[2][1] + D[3][1];
            s2 = D[2][2] + D[3][2];
            s3 = D[2][3] + D[3][3];
            gso[g * GSP + nc0 + 8 + tig * 2 + 0] = s0;
            gso[g * GSP + nc0 + 8 + tig * 2 + 1] = s1;
            gso[(g + 8) * GSP + nc0 + 8 + tig * 2 + 0] = s2;
            gso[(g + 8) * GSP + nc0 + 8 + tig * 2 + 1] = s3;
        }
        __syncthreads();

        // ---- update: sum k-halves + xp, activate, bf16 h store ----
        {
            const float* g0 = gs2 + ub * GSP;
            const float* g1 = gs2 + 16 * GSP + ub * GSP;
            float gi = g0[ 0 + uj] + g1[ 0 + uj] + xvi;
            float gf = g0[16 + uj] + g1[16 + uj] + xvf;
            float gg = g0[32 + uj] + g1[32 + uj] + xvg;
            float go = g0[48 + uj] + g1[48 + uj] + xvo;
            float i_ = sigf(gi), f_ = sigf(gf);
            float gv = tanhf_fast(gg), o_ = sigf(go);
            cstate = fmaf(f_, cstate, i_ * gv);
            float h = o_ * tanhf_fast(cstate);
            if (t & 1) *hh0 = __float2bfloat16(h);
            else       *hh1 = __float2bfloat16(h);
            if (t == SEQ - 1)
                g_last[batch * (2 * HDIM) + jcol] = h;
            else {
                const size_t off = tstride * (size_t)(t + 1);
                xvi = __ldcs(xpi + off); xvf = __ldcs(xpf + off);
                xvg = __ldcs(xpg + off); xvo = __ldcs(xpo + off);
            }
        }

        if (t < SEQ - 1)
            FLAGBAR(t + 1);
    }
}

// ================================================================
// Kernel 3b: reset barrier flags (stream-ordered after the scan).
// ================================================================
__global__ void reset_flags_kernel()
{
    if (threadIdx.x < 128) g_flags[threadIdx.x][0] = 0ull;
}

// ================================================================
// Kernel 4: final FC (unchanged).
// ================================================================
__global__ void __launch_bounds__(512) fc_kernel(
    const float* __restrict__ Wfc, const float* __restrict__ bfc,
    float* __restrict__ out)
{
    __shared__ float ls[2 * HDIM];
    const int b = blockIdx.x, tid = threadIdx.x;
    if (tid < 256)
        ((float4*)ls)[tid] = ((const float4*)(g_last + (size_t)b * 2 * HDIM))[tid];
    __syncthreads();

    const int o = tid >> 2, q = tid & 3;
    const float4* wp = (const float4*)(Wfc + (size_t)o * (2 * HDIM)) + q * 64;
    const float4* lv = (const float4*)ls + q * 64;
    float acc = 0.f;
#pragma unroll 16
    for (int k = 0; k < 64; k++) {
        float4 w = __ldg(wp + k);
        float4 l = lv[k];
        acc += w.x * l.x + w.y * l.y + w.z * l.z + w.w * l.w;
    }
    acc += __shfl_xor_sync(0xffffffff, acc, 1);
    acc += __shfl_xor_sync(0xffffffff, acc, 2);
    if (q == 0) out[b * ODIM + o] = acc + bfc[o];
}

// ================================================================
extern "C" void kernel_launch(void* const* d_in, const int* in_sizes, int n_in,
                              void* d_out, int out_size)
{
    const float* x      = (const float*)d_in[0];
    const float* W_ih_f = (const float*)d_in[1];
    const float* W_hh_f = (const float*)d_in[2];
    const float* b_f    = (const float*)d_in[3];
    const float* W_ih_b = (const float*)d_in[4];
    const float* b_b    = (const float*)d_in[6];
    const float* W_fc   = (const float*)d_in[7];
    const float* b_fc   = (const float*)d_in[8];
    float* out = (float*)d_out;

    cudaFuncSetAttribute(gemm_xp_kernel,
                         cudaFuncAttributeMaxDynamicSharedMemorySize, XGEMM_SMEM);
    cudaFuncSetAttribute(lstm_scan_kernel,
                         cudaFuncAttributeMaxDynamicSharedMemorySize, SCAN_SMEM);

    gemm_xp_kernel<<<dim3(G4 / XBN, SEQ / 2), 256, XGEMM_SMEM>>>(x, W_ih_f, b_f);
    bwd_last_kernel<<<dim3(BATCH, 2), 256>>>(x, W_ih_b, b_b);
    lstm_scan_kernel<<<SCAN_BLOCKS, SCAN_THREADS, SCAN_SMEM>>>(W_hh_f);
    reset_flags_kernel<<<1, 128>>>();
    fc_kernel<<<BATCH, 512>>>(W_fc, b_fc, out);
}

// round 16
// speedup vs baseline: 1.3926x; 1.1159x over previous
#include <cuda_runtime.h>
#include <cuda_bf16.h>
#include <cstdint>

#define BATCH 64
#define SEQ   1024
#define IDIM  256
#define HDIM  512
#define ODIM  128
#define G4    2048

typedef unsigned long long ull;

// ---------------- device scratch ----------------
__device__ float g_xp[(size_t)SEQ * BATCH * G4];          // input projection [t*64+b][4H]
__device__ __nv_bfloat16 g_hh[2][BATCH * HDIM];           // h (bf16), double-buffered
__device__ float g_last[BATCH * 2 * HDIM];
__device__ ull g_flags[128][16];                          // padded barrier flags

__device__ __forceinline__ float sigf(float v) {
    return __fdividef(1.0f, 1.0f + __expf(-v));
}
__device__ __forceinline__ float tanhf_fast(float v) {
    float e = __expf(2.0f * v);
    return __fdividef(e - 1.0f, e + 1.0f);
}
__device__ __forceinline__ uint32_t packbf2(__nv_bfloat16 lo_elem, __nv_bfloat16 hi_elem) {
    return (uint32_t)__bfloat16_as_ushort(lo_elem) |
           ((uint32_t)__bfloat16_as_ushort(hi_elem) << 16);
}
__device__ __forceinline__ void mma16816(
    float& d0, float& d1, float& d2, float& d3,
    uint32_t a0, uint32_t a1, uint32_t a2, uint32_t a3,
    uint32_t b0, uint32_t b1)
{
    asm volatile(
        "mma.sync.aligned.m16n8k16.row.col.f32.bf16.bf16.f32 "
        "{%0,%1,%2,%3},{%4,%5,%6,%7},{%8,%9},{%0,%1,%2,%3};"
        : "+f"(d0), "+f"(d1), "+f"(d2), "+f"(d3)
        : "r"(a0), "r"(a1), "r"(a2), "r"(a3), "r"(b0), "r"(b1));
}

// ================================================================
// Kernel 1: xp = relu(x) @ W_ih_f^T + b_f  — TC, block 128x128x64.
// BN=128 halves the number of times each x tile is re-read from L2.
// 8 warps: warp tile 32(M) x 64(N); 64 fp32 accumulators.
// ================================================================
#define XBM 128
#define XBN 128
#define XBK 64
#define XST 36
#define XGEMM_SMEM ((2*XBM*XST + 2*XBN*XST) * 4)

__global__ void __launch_bounds__(256, 2) gemm_xp_kernel(
    const float* __restrict__ x,
    const float* __restrict__ Wih, const float* __restrict__ bias)
{
    extern __shared__ uint32_t smx[];
    uint32_t* Ah = smx;                        // [128][XST]
    uint32_t* Al = Ah + XBM * XST;
    uint32_t* Bh = Al + XBM * XST;             // [128][XST]
    uint32_t* Bl = Bh + XBN * XST;

    const int tid  = threadIdx.x;
    const int lane = tid & 31, wid = tid >> 5;
    const int n0 = blockIdx.x * XBN;
    const int t0 = blockIdx.y * 2;

    const int mw = wid >> 1;      // 0..3  (32 M-rows each)
    const int nw = wid & 1;       // 0..1  (64 N-cols each)
    const int g = lane >> 2, tig = lane & 3;

    float C[2][8][4];
#pragma unroll
    for (int mt = 0; mt < 2; mt++)
#pragma unroll
        for (int nt = 0; nt < 8; nt++)
            C[mt][nt][0] = C[mt][nt][1] = C[mt][nt][2] = C[mt][nt][3] = 0.f;

#pragma unroll 1
    for (int ko = 0; ko < IDIM; ko += XBK) {
        // ---- stage A (relu + hi/lo split): 8 float4 per thread ----
#pragma unroll
        for (int i = 0; i < 8; i++) {
            int u = tid + i * 256;
            int row = u >> 4, q = u & 15;
            int b = row & 63, tt = t0 + (row >> 6);
            float4 v = __ldcg((const float4*)(x + ((size_t)b * SEQ + tt) * IDIM + ko + q * 4));
            v.x = fmaxf(v.x, 0.f); v.y = fmaxf(v.y, 0.f);
            v.z = fmaxf(v.z, 0.f); v.w = fmaxf(v.w, 0.f);
            __nv_bfloat16 h0 = __float2bfloat16(v.x), h1 = __float2bfloat16(v.y);
            __nv_bfloat16 h2 = __float2bfloat16(v.z), h3 = __float2bfloat16(v.w);
            __nv_bfloat16 l0 = __float2bfloat16(v.x - __bfloat162float(h0));
            __nv_bfloat16 l1 = __float2bfloat16(v.y - __bfloat162float(h1));
            __nv_bfloat16 l2 = __float2bfloat16(v.z - __bfloat162float(h2));
            __nv_bfloat16 l3 = __float2bfloat16(v.w - __bfloat162float(h3));
            *(uint2*)(Ah + row * XST + q * 2) = make_uint2(packbf2(h0, h1), packbf2(h2, h3));
            *(uint2*)(Al + row * XST + q * 2) = make_uint2(packbf2(l0, l1), packbf2(l2, l3));
        }
        // ---- stage B (hi/lo split): 8 float4 per thread (128 rows) ----
#pragma unroll
        for (int i = 0; i < 8; i++) {
            int u = tid + i * 256;
            int row = u >> 4, q = u & 15;
            float4 v = __ldcg((const float4*)(Wih + (size_t)(n0 + row) * IDIM + ko + q * 4));
            __nv_bfloat16 h0 = __float2bfloat16(v.x), h1 = __float2bfloat16(v.y);
            __nv_bfloat16 h2 = __float2bfloat16(v.z), h3 = __float2bfloat16(v.w);
            __nv_bfloat16 l0 = __float2bfloat16(v.x - __bfloat162float(h0));
            __nv_bfloat16 l1 = __float2bfloat16(v.y - __bfloat162float(h1));
            __nv_bfloat16 l2 = __float2bfloat16(v.z - __bfloat162float(h2));
            __nv_bfloat16 l3 = __float2bfloat16(v.w - __bfloat162float(h3));
            *(uint2*)(Bh + row * XST + q * 2) = make_uint2(packbf2(h0, h1), packbf2(h2, h3));
            *(uint2*)(Bl + row * XST + q * 2) = make_uint2(packbf2(l0, l1), packbf2(l2, l3));
        }
        __syncthreads();

        // ---- MMA: 4 k16-steps x (2 m-tiles x 8 n-tiles x 3 variants) ----
#pragma unroll
        for (int ks = 0; ks < 4; ks++) {
            int w = ks * 8;
            uint32_t ah[2][4], al[2][4];
#pragma unroll
            for (int mt = 0; mt < 2; mt++) {
                int r0 = (mw * 32 + mt * 16 + g) * XST + w + tig;
                int r1 = r0 + 8 * XST;
                ah[mt][0] = Ah[r0]; ah[mt][1] = Ah[r1];
                ah[mt][2] = Ah[r0 + 4]; ah[mt][3] = Ah[r1 + 4];
                al[mt][0] = Al[r0]; al[mt][1] = Al[r1];
                al[mt][2] = Al[r0 + 4]; al[mt][3] = Al[r1 + 4];
            }
#pragma unroll
            for (int nt = 0; nt < 8; nt++) {
                int c = (nw * 64 + nt * 8 + g) * XST + w + tig;
                uint32_t bh0 = Bh[c], bh1 = Bh[c + 4];
                uint32_t bl0 = Bl[c], bl1 = Bl[c + 4];
#pragma unroll
                for (int mt = 0; mt < 2; mt++) {
                    mma16816(C[mt][nt][0], C[mt][nt][1], C[mt][nt][2], C[mt][nt][3],
                             ah[mt][0], ah[mt][1], ah[mt][2], ah[mt][3], bh0, bh1);
                    mma16816(C[mt][nt][0], C[mt][nt][1], C[mt][nt][2], C[mt][nt][3],
                             al[mt][0], al[mt][1], al[mt][2], al[mt][3], bh0, bh1);
                    mma16816(C[mt][nt][0], C[mt][nt][1], C[mt][nt][2], C[mt][nt][3],
                             ah[mt][0], ah[mt][1], ah[mt][2], ah[mt][3], bl0, bl1);
                }
            }
        }
        __syncthreads();
    }

    // ---- epilogue: bias + store float2 per fragment row ----
#pragma unroll
    for (int mt = 0; mt < 2; mt++) {
#pragma unroll
        for (int nt = 0; nt < 8; nt++) {
            int col = n0 + nw * 64 + nt * 8 + tig * 2;
            float2 bv = *(const float2*)(bias + col);
            int ml = mw * 32 + mt * 16 + g;
            int rowg = (t0 + (ml >> 6)) * BATCH + (ml & 63);
            float2 o0 = { C[mt][nt][0] + bv.x, C[mt][nt][1] + bv.y };
            *(float2*)(g_xp + (size_t)rowg * G4 + col) = o0;
            ml += 8;
            rowg = (t0 + (ml >> 6)) * BATCH + (ml & 63);
            float2 o1 = { C[mt][nt][2] + bv.x, C[mt][nt][3] + bv.y };
            *(float2*)(g_xp + (size_t)rowg * G4 + col) = o1;
        }
    }
}

// ================================================================
// Kernel 2: backward-direction last hidden state (unchanged)
// ================================================================
__global__ void __launch_bounds__(256) bwd_last_kernel(
    const float* __restrict__ x,
    const float* __restrict__ Wb, const float* __restrict__ bb)
{
    __shared__ float xs[IDIM];
    const int b = blockIdx.x, tid = threadIdx.x;
    xs[tid] = fmaxf(x[((size_t)b * SEQ + (SEQ - 1)) * IDIM + tid], 0.f);
    __syncthreads();

    const int j = blockIdx.y * 256 + tid;
    const int cols[3] = { j, 2 * HDIM + j, 3 * HDIM + j };
    float acc[3] = { bb[cols[0]], bb[cols[1]], bb[cols[2]] };
#pragma unroll
    for (int gi = 0; gi < 3; gi++) {
        const float4* wp = (const float4*)(Wb + (size_t)cols[gi] * IDIM);
        float s = 0.f;
#pragma unroll 8
        for (int k4 = 0; k4 < IDIM / 4; k4++) {
            float4 w = __ldg(wp + k4);
            float4 xv = *(const float4*)&xs[k4 * 4];
            s += w.x * xv.x + w.y * xv.y + w.z * xv.z + w.w * xv.w;
        }
        acc[gi] += s;
    }
    float cst = sigf(acc[0]) * tanhf_fast(acc[1]);
    float h   = sigf(acc[2]) * tanhf_fast(cst);
    g_last[b * (2 * HDIM) + HDIM + j] = h;
}

// ================================================================
// Kernel 3: persistent LSTM scan — producer-granular barrier.
// Same structure/arithmetic as R15 (h single bf16 plane, W hi/lo,
// kh x nw warp split). Change: the end-of-step FLAGBAR is split
// into RELEASE-only (after h stores) and a PER-WARP wait at the
// start of staging: warp w waits ONLY on its 4 assigned producers
// (flags fbase+4w..4w+3), then stages their 512B chunks. The
// post-staging __syncthreads joins the block, so the union of
// warps still covers all 32 producers (same WAR guarantees as the
// full barrier) while stage loads overlap straggler waits.
// ================================================================
#define SCAN_BLOCKS 128
#define SCAN_THREADS 256
#define WST 260                 // words per 512-elem bf16 row (256 + 4 pad)
#define GSP 68
#define SCAN_SMEM ((2*64*WST + 16*WST + 2*16*GSP) * 4)

__global__ void __launch_bounds__(SCAN_THREADS, 1) lstm_scan_kernel(const float* __restrict__ Whh)
{
    extern __shared__ uint32_t smw[];
    uint32_t* ws_hi = smw;                    // [64][WST]
    uint32_t* ws_lo = smw + 64 * WST;
    uint32_t* hs    = smw + 2 * 64 * WST;     // [16][WST] h (bf16)
    float*    gs2   = (float*)(hs + 16 * WST);  // [2][16][GSP]

    const int tid  = threadIdx.x;
    const int bid  = blockIdx.x;
    const int bg   = bid >> 5;
    const int jg   = bid & 31;
    const int fbase = bg * 32;
    const int lane = tid & 31;
    const int wid  = tid >> 5;

    // ---- one-time W_hh slice load + hi/lo split ----
#pragma unroll 1
    for (int u = tid; u < 64 * 256; u += SCAN_THREADS) {
        int lc = u >> 8;
        int w  = u & 255;
        int grow = (lc >> 4) * HDIM + jg * 16 + (lc & 15);
        float2 v = *(const float2*)(Whh + (size_t)grow * HDIM + w * 2);
        __nv_bfloat16 h0 = __float2bfloat16(v.x);
        __nv_bfloat16 h1 = __float2bfloat16(v.y);
        __nv_bfloat16 l0 = __float2bfloat16(v.x - __bfloat162float(h0));
        __nv_bfloat16 l1 = __float2bfloat16(v.y - __bfloat162float(h1));
        ws_hi[lc * WST + w] = packbf2(h0, h1);
        ws_lo[lc * WST + w] = packbf2(l0, l1);
    }

    const int g   = lane >> 2, tig = lane & 3;
    const int kh  = wid >> 2;
    const int nw  = wid & 3;
    const int nc0 = nw * 16;
    const int hb0 = g * WST + tig;
    const int hb1 = (g + 8) * WST + tig;
    const int wb0 = (nc0 + g) * WST + tig;
    const int wb1 = (nc0 + 8 + g) * WST + tig;
    const int kw0 = kh * 128;
    float* gso = gs2 + kh * 16 * GSP;

    const int ub = tid >> 4, uj = tid & 15;
    const int batch = bg * 16 + ub;
    const int jcol  = jg * 16 + uj;
    float cstate = 0.f;
    __nv_bfloat16* hh0 = &g_hh[0][batch * HDIM + jcol];
    __nv_bfloat16* hh1 = &g_hh[1][batch * HDIM + jcol];
    const size_t tstride = (size_t)BATCH * G4;
    const float* xpi = g_xp + (size_t)batch * G4 + 0 * HDIM + jcol;
    const float* xpf = g_xp + (size_t)batch * G4 + 1 * HDIM + jcol;
    const float* xpg = g_xp + (size_t)batch * G4 + 2 * HDIM + jcol;
    const float* xpo = g_xp + (size_t)batch * G4 + 3 * HDIM + jcol;
    float xvi = __ldcs(xpi), xvf = __ldcs(xpf);
    float xvg = __ldcs(xpg), xvo = __ldcs(xpo);

    // staging role: warp w owns producers 4w..4w+3; lane -> (row, half)
    const int srow = lane >> 1, shalf = lane & 1;
    const int pflag = fbase + (wid << 2) + (lane & 3);

    // ---- t = 0: h = 0 -> gates = xp ----
    {
        float i_ = sigf(xvi), f_ = sigf(xvf);
        float gv = tanhf_fast(xvg), o_ = sigf(xvo);
        cstate = fmaf(f_, cstate, i_ * gv);
        float h = o_ * tanhf_fast(cstate);
        *hh1 = __float2bfloat16(h);
        xvi = __ldcs(xpi + tstride); xvf = __ldcs(xpf + tstride);
        xvg = __ldcs(xpg + tstride); xvo = __ldcs(xpo + tstride);
    }

#define RELEASE(VAL) do{                                                       \
    __syncthreads();                                                           \
    if (tid == 0)                                                              \
        asm volatile("st.release.gpu.global.u64 [%0], %1;"                     \
                     :: "l"(&g_flags[bid][0]), "l"((ull)(VAL)) : "memory");    \
}while(0)

    RELEASE(1);

#pragma unroll 1
    for (int t = 1; t < SEQ; t++) {
        // ---- per-warp wait on this warp's 4 producers (flags >= t) ----
        {
            ull v;
            do {
                asm volatile("ld.acquire.gpu.global.u64 %0, [%1];"
                             : "=l"(v) : "l"(&g_flags[pflag][0]) : "memory");
            } while (v < (ull)t);
            __syncwarp();
        }
        // ---- stage this warp's 4 producer chunks (16 rows x 32B each) ----
        {
            const __nv_bfloat16* hbase = g_hh[t & 1] + (size_t)bg * 16 * HDIM
                                         + (size_t)srow * HDIM + shalf * 8;
            uint32_t* hdst2 = hs + srow * WST + shalf * 4;
#pragma unroll
            for (int pp = 0; pp < 4; pp++) {
                int p = (wid << 2) + pp;
                uint4 v = __ldcg((const uint4*)(hbase + p * 16));
                *(uint4*)(hdst2 + p * 8) = v;
            }
        }
        __syncthreads();

        // ---- dots: 16 k-tiles x 2 n-tiles x 2 variants (h*Whi + h*Wlo) ----
        float D[4][4];
#pragma unroll
        for (int i = 0; i < 4; i++)
            D[i][0] = D[i][1] = D[i][2] = D[i][3] = 0.f;

#pragma unroll 4
        for (int j = 0; j < 16; j++) {
            int w = kw0 + j * 8;
            uint32_t ah0 = hs[hb0 + w],     ah1 = hs[hb1 + w];
            uint32_t ah2 = hs[hb0 + w + 4], ah3 = hs[hb1 + w + 4];
            uint32_t bh00 = ws_hi[wb0 + w], bh01 = ws_hi[wb0 + w + 4];
            uint32_t bl00 = ws_lo[wb0 + w], bl01 = ws_lo[wb0 + w + 4];
            uint32_t bh10 = ws_hi[wb1 + w], bh11 = ws_hi[wb1 + w + 4];
            uint32_t bl10 = ws_lo[wb1 + w], bl11 = ws_lo[wb1 + w + 4];
            mma16816(D[0][0], D[0][1], D[0][2], D[0][3], ah0, ah1, ah2, ah3, bh00, bh01);
            mma16816(D[1][0], D[1][1], D[1][2], D[1][3], ah0, ah1, ah2, ah3, bl00, bl01);
            mma16816(D[2][0], D[2][1], D[2][2], D[2][3], ah0, ah1, ah2, ah3, bh10, bh11);
            mma16816(D[3][0], D[3][1], D[3][2], D[3][3], ah0, ah1, ah2, ah3, bl10, bl11);
        }

        // ---- epilogue: combine variants, store to this k-half's gs plane ----
        {
            float s0, s1, s2, s3;
            s0 = D[0][0] + D[1][0];
            s1 = D[0][1] + D[1][1];
            s2 = D[0][2] + D[1][2];
            s3 = D[0][3] + D[1][3];
            gso[g * GSP + nc0 + tig * 2 + 0] = s0;
            gso[g * GSP + nc0 + tig * 2 + 1] = s1;
            gso[(g + 8) * GSP + nc0 + tig * 2 + 0] = s2;
            gso[(g + 8) * GSP + nc0 + tig * 2 + 1] = s3;
            s0 = D[2][0] + D[3][0];
            s1 = D[2][1] + D[3][1];
            s2 = D[2][2] + D[3][2];
            s3 = D[2][3] + D[3][3];
            gso[g * GSP + nc0 + 8 + tig * 2 + 0] = s0;
            gso[g * GSP + nc0 + 8 + tig * 2 + 1] = s1;
            gso[(g + 8) * GSP + nc0 + 8 + tig * 2 + 0] = s2;
            gso[(g + 8) * GSP + nc0 + 8 + tig * 2 + 1] = s3;
        }
        __syncthreads();

        // ---- update: sum k-halves + xp, activate, bf16 h store ----
        {
            const float* g0 = gs2 + ub * GSP;
            const float* g1 = gs2 + 16 * GSP + ub * GSP;
            float gi = g0[ 0 + uj] + g1[ 0 + uj] + xvi;
            float gf = g0[16 + uj] + g1[16 + uj] + xvf;
            float gg = g0[32 + uj] + g1[32 + uj] + xvg;
            float go = g0[48 + uj] + g1[48 + uj] + xvo;
            float i_ = sigf(gi), f_ = sigf(gf);
            float gv = tanhf_fast(gg), o_ = sigf(go);
            cstate = fmaf(f_, cstate, i_ * gv);
            float h = o_ * tanhf_fast(cstate);
            if (t & 1) *hh0 = __float2bfloat16(h);
            else       *hh1 = __float2bfloat16(h);
            if (t == SEQ - 1)
                g_last[batch * (2 * HDIM) + jcol] = h;
            else {
                const size_t off = tstride * (size_t)(t + 1);
                xvi = __ldcs(xpi + off); xvf = __ldcs(xpf + off);
                xvg = __ldcs(xpg + off); xvo = __ldcs(xpo + off);
            }
        }

        if (t < SEQ - 1)
            RELEASE(t + 1);
    }
}

// ================================================================
// Kernel 3b: reset barrier flags (stream-ordered after the scan).
// ================================================================
__global__ void reset_flags_kernel()
{
    if (threadIdx.x < 128) g_flags[threadIdx.x][0] = 0ull;
}

// ================================================================
// Kernel 4: final FC (unchanged).
// ================================================================
__global__ void __launch_bounds__(512) fc_kernel(
    const float* __restrict__ Wfc, const float* __restrict__ bfc,
    float* __restrict__ out)
{
    __shared__ float ls[2 * HDIM];
    const int b = blockIdx.x, tid = threadIdx.x;
    if (tid < 256)
        ((float4*)ls)[tid] = ((const float4*)(g_last + (size_t)b * 2 * HDIM))[tid];
    __syncthreads();

    const int o = tid >> 2, q = tid & 3;
    const float4* wp = (const float4*)(Wfc + (size_t)o * (2 * HDIM)) + q * 64;
    const float4* lv = (const float4*)ls + q * 64;
    float acc = 0.f;
#pragma unroll 16
    for (int k = 0; k < 64; k++) {
        float4 w = __ldg(wp + k);
        float4 l = lv[k];
        acc += w.x * l.x + w.y * l.y + w.z * l.z + w.w * l.w;
    }
    acc += __shfl_xor_sync(0xffffffff, acc, 1);
    acc += __shfl_xor_sync(0xffffffff, acc, 2);
    if (q == 0) out[b * ODIM + o] = acc + bfc[o];
}

// ================================================================
extern "C" void kernel_launch(void* const* d_in, const int* in_sizes, int n_in,
                              void* d_out, int out_size)
{
    const float* x      = (const float*)d_in[0];
    const float* W_ih_f = (const float*)d_in[1];
    const float* W_hh_f = (const float*)d_in[2];
    const float* b_f    = (const float*)d_in[3];
    const float* W_ih_b = (const float*)d_in[4];
    const float* b_b    = (const float*)d_in[6];
    const float* W_fc   = (const float*)d_in[7];
    const float* b_fc   = (const float*)d_in[8];
    float* out = (float*)d_out;

    cudaFuncSetAttribute(gemm_xp_kernel,
                         cudaFuncAttributeMaxDynamicSharedMemorySize, XGEMM_SMEM);
    cudaFuncSetAttribute(lstm_scan_kernel,
                         cudaFuncAttributeMaxDynamicSharedMemorySize, SCAN_SMEM);

    gemm_xp_kernel<<<dim3(G4 / XBN, SEQ / 2), 256, XGEMM_SMEM>>>(x, W_ih_f, b_f);
    bwd_last_kernel<<<dim3(BATCH, 2), 256>>>(x, W_ih_b, b_b);
    lstm_scan_kernel<<<SCAN_BLOCKS, SCAN_THREADS, SCAN_SMEM>>>(W_hh_f);
    reset_flags_kernel<<<1, 128>>>();
    fc_kernel<<<BATCH, 512>>>(W_fc, b_fc, out);
}